// round 1
// baseline (speedup 1.0000x reference)
#include <cuda_runtime.h>
#include <math.h>

#define NN 8192
#define DD 256
#define HH 64

// Scratch (no allocations allowed): per-node gate e, and W1 transposed.
__device__ float g_e[NN];
__device__ float g_W1T[HH * DD];

// ---------------------------------------------------------------------------
// Kernel 0: transpose W1 [D,H] -> W1T [H,D] so the MLP can use float4 k-loads.
// ---------------------------------------------------------------------------
__global__ void transpose_w1_kernel(const float* __restrict__ W1) {
    int idx = blockIdx.x * blockDim.x + threadIdx.x;  // over D*H = 16384
    if (idx < DD * HH) {
        int k = idx / HH;   // 0..255
        int j = idx % HH;   // 0..63
        g_W1T[j * DD + k] = W1[idx];
    }
}

// ---------------------------------------------------------------------------
// Kernel 1: e = sigmoid(relu(h @ W1 + b1) @ W2 + b2)   [N]
// Block: 256 threads, handles ROWS=32 node rows.
//   tid -> j = tid & 63 (hidden unit), rg = tid >> 6 (row group of 8 rows)
// h rows staged in smem (32 KB); W1T read via float4 from L2/L1.
// ---------------------------------------------------------------------------
#define ROWS 32
__global__ void mlp_kernel(const float* __restrict__ h,
                           const float* __restrict__ b1,
                           const float* __restrict__ W2,
                           const float* __restrict__ b2,
                           float* __restrict__ out_e) {
    __shared__ float sh_h[ROWS * DD];          // 32 KB
    __shared__ float sh_t[ROWS][HH + 1];       // padded, ~8.1 KB

    const int tid = threadIdx.x;
    const int rowbase = blockIdx.x * ROWS;

    // Stage 32 contiguous h rows (32*256 floats = 2048 float4), coalesced.
    {
        const float4* src = (const float4*)(h + (size_t)rowbase * DD);
        float4* dst = (float4*)sh_h;
        #pragma unroll
        for (int i = tid; i < ROWS * DD / 4; i += 256) dst[i] = src[i];
    }
    __syncthreads();

    const int j  = tid & 63;
    const int rg = tid >> 6;   // 0..3, each group owns 8 rows

    float acc[8];
    const float bj = b1[j];
    #pragma unroll
    for (int r = 0; r < 8; r++) acc[r] = bj;

    const float4* w1t = (const float4*)(g_W1T + j * DD);
    const float4* sh4 = (const float4*)sh_h;

    #pragma unroll 2
    for (int k4 = 0; k4 < DD / 4; k4++) {
        const float4 w = w1t[k4];
        #pragma unroll
        for (int r = 0; r < 8; r++) {
            const float4 hv = sh4[(rg * 8 + r) * (DD / 4) + k4];
            acc[r] = fmaf(w.x, hv.x,
                     fmaf(w.y, hv.y,
                     fmaf(w.z, hv.z,
                     fmaf(w.w, hv.w, acc[r]))));
        }
    }

    const float w2j = W2[j];
    #pragma unroll
    for (int r = 0; r < 8; r++)
        sh_t[rg * 8 + r][j] = fmaxf(acc[r], 0.0f) * w2j;
    __syncthreads();

    if (tid < ROWS) {
        float s = b2[0];
        #pragma unroll
        for (int jj = 0; jj < HH; jj++) s += sh_t[tid][jj];
        const float ev = 1.0f / (1.0f + expf(-s));
        g_e[rowbase + tid]  = ev;
        out_e[rowbase + tid] = ev;
    }
}

// ---------------------------------------------------------------------------
// Kernel 2: h_out[i,:] = sum_j (A[i,j] > 0) * e[j] * h[j,:]
// One block per row i, 256 threads (== D). Per 2048-entry chunk of A-row:
//   phase 1: streamed (__ldcs, non-temporal) float4 scan + compact nnz to smem
//   phase 2: all threads accumulate coalesced h[j][tid] (L2-resident h)
// A (256 MB) is read exactly once -> DRAM-bound by construction.
// ---------------------------------------------------------------------------
#define CHUNK 2048
__global__ void agg_kernel(const float* __restrict__ A,
                           const float* __restrict__ h,
                           float* __restrict__ out) {
    __shared__ int   s_idx[CHUNK];
    __shared__ float s_coef[CHUNK];
    __shared__ int   s_count;

    const int row = blockIdx.x;
    const int tid = threadIdx.x;

    float acc = 0.0f;
    const float4* Arow = (const float4*)(A + (size_t)row * NN);

    for (int base = 0; base < NN; base += CHUNK) {
        if (tid == 0) s_count = 0;
        __syncthreads();

        // Phase 1: scan + compact. 2048 floats / 256 threads = 2 float4 each.
        #pragma unroll
        for (int v = 0; v < CHUNK / (256 * 4); v++) {
            const int vec = (base >> 2) + v * 256 + tid;
            const float4 a = __ldcs(Arow + vec);   // streaming: don't pollute L2
            const int j0 = vec << 2;
            if (a.x > 0.0f) { int p = atomicAdd(&s_count, 1); s_idx[p] = j0;     s_coef[p] = g_e[j0];     }
            if (a.y > 0.0f) { int p = atomicAdd(&s_count, 1); s_idx[p] = j0 + 1; s_coef[p] = g_e[j0 + 1]; }
            if (a.z > 0.0f) { int p = atomicAdd(&s_count, 1); s_idx[p] = j0 + 2; s_coef[p] = g_e[j0 + 2]; }
            if (a.w > 0.0f) { int p = atomicAdd(&s_count, 1); s_idx[p] = j0 + 3; s_coef[p] = g_e[j0 + 3]; }
        }
        __syncthreads();

        // Phase 2: accumulate. 4-way unroll for memory-level parallelism.
        const int cnt = s_count;
        int k = 0;
        for (; k + 4 <= cnt; k += 4) {
            const float c0 = s_coef[k],     c1 = s_coef[k + 1];
            const float c2 = s_coef[k + 2], c3 = s_coef[k + 3];
            const float v0 = h[(size_t)s_idx[k]     * DD + tid];
            const float v1 = h[(size_t)s_idx[k + 1] * DD + tid];
            const float v2 = h[(size_t)s_idx[k + 2] * DD + tid];
            const float v3 = h[(size_t)s_idx[k + 3] * DD + tid];
            acc = fmaf(c0, v0, acc);
            acc = fmaf(c1, v1, acc);
            acc = fmaf(c2, v2, acc);
            acc = fmaf(c3, v3, acc);
        }
        for (; k < cnt; k++)
            acc = fmaf(s_coef[k], h[(size_t)s_idx[k] * DD + tid], acc);
        __syncthreads();
    }

    out[(size_t)row * DD + tid] = acc;
}

// ---------------------------------------------------------------------------
// Launch: inputs in setup_inputs order:
//   0: graph_info [N*N], 1: h [N*D], 2: W1 [D*H], 3: b1 [H], 4: W2 [H], 5: b2 [1]
// Output: h_out [N*D] followed by e [N].
// ---------------------------------------------------------------------------
extern "C" void kernel_launch(void* const* d_in, const int* in_sizes, int n_in,
                              void* d_out, int out_size) {
    const float* A  = (const float*)d_in[0];
    const float* h  = (const float*)d_in[1];
    const float* W1 = (const float*)d_in[2];
    const float* b1 = (const float*)d_in[3];
    const float* W2 = (const float*)d_in[4];
    const float* b2 = (const float*)d_in[5];

    float* out   = (float*)d_out;
    float* out_h = out;                 // [N*D]
    float* out_e = out + (size_t)NN * DD;  // [N]

    transpose_w1_kernel<<<(DD * HH + 255) / 256, 256>>>(W1);
    mlp_kernel<<<NN / ROWS, 256>>>(h, b1, W2, b2, out_e);
    agg_kernel<<<NN, 256>>>(A, h, out_h);
}

// round 2
// speedup vs baseline: 1.1684x; 1.1684x over previous
#include <cuda_runtime.h>
#include <cuda_fp16.h>
#include <math.h>

#define NN 8192
#define DD 256
#define HH 64

// Pre-scaled features: he[j, d] = e_j * h[j, d], fp16 (4 MB, stays L2-resident).
__device__ __half g_he[NN * DD];

// ---------------------------------------------------------------------------
// Kernel 1: MLP gate + he emission.
//   e = sigmoid(relu(h @ W1 + b1) @ W2 + b2)
// Block: 256 threads = 16 row-groups (x4 rows) x 16 j-groups (x4 hidden).
// W1 staged in smem [k][j] (identity copy, conflict-free float4-over-j reads),
// h read via __ldg float4 (L1, 16-way broadcast reuse).
// ---------------------------------------------------------------------------
#define MLP_ROWS 64
__global__ void __launch_bounds__(256) mlp_kernel(
    const float* __restrict__ h, const float* __restrict__ W1,
    const float* __restrict__ b1, const float* __restrict__ W2,
    const float* __restrict__ b2, float* __restrict__ out_e) {

  __shared__ float sW[128 * HH];          // half of K at a time: 32 KB
  __shared__ float sPart[MLP_ROWS][17];   // per-(row, jg) partials
  __shared__ float sE[MLP_ROWS];

  const int tid = threadIdx.x;
  const int rg = tid >> 4;                // 0..15
  const int jg = tid & 15;                // 0..15
  const int rowbase = blockIdx.x * MLP_ROWS;
  const int r0 = rg * 4;                  // local row base
  const int j0 = jg * 4;                  // hidden base

  float acc[4][4];
  {
    float bj0 = __ldg(&b1[j0]),     bj1 = __ldg(&b1[j0 + 1]);
    float bj2 = __ldg(&b1[j0 + 2]), bj3 = __ldg(&b1[j0 + 3]);
    #pragma unroll
    for (int a = 0; a < 4; a++) {
      acc[a][0] = bj0; acc[a][1] = bj1; acc[a][2] = bj2; acc[a][3] = bj3;
    }
  }

  const float4* h4 = (const float4*)(h + (size_t)rowbase * DD);
  const float4* sW4 = (const float4*)sW;

  for (int half = 0; half < 2; half++) {
    __syncthreads();
    // Stage W1[k in half*128 .. +128][all 64 j] -> sW (identity layout).
    for (int i = tid; i < 128 * HH; i += 256)
      sW[i] = W1[half * 128 * HH + i];
    __syncthreads();

    #pragma unroll 4
    for (int k4 = 0; k4 < 32; k4++) {
      const int kg = half * 32 + k4;      // global k-vec index
      float4 hv[4];
      #pragma unroll
      for (int a = 0; a < 4; a++)
        hv[a] = __ldg(&h4[(size_t)(r0 + a) * (DD / 4) + kg]);

      // w rows for k = k4*4 .. +3, float4 over j (16B-aligned, conflict-free)
      const float4 wA = sW4[(k4 * 4 + 0) * 16 + jg];
      const float4 wB = sW4[(k4 * 4 + 1) * 16 + jg];
      const float4 wC = sW4[(k4 * 4 + 2) * 16 + jg];
      const float4 wD = sW4[(k4 * 4 + 3) * 16 + jg];

      #pragma unroll
      for (int a = 0; a < 4; a++) {
        acc[a][0] = fmaf(hv[a].x, wA.x, fmaf(hv[a].y, wB.x, fmaf(hv[a].z, wC.x, fmaf(hv[a].w, wD.x, acc[a][0]))));
        acc[a][1] = fmaf(hv[a].x, wA.y, fmaf(hv[a].y, wB.y, fmaf(hv[a].z, wC.y, fmaf(hv[a].w, wD.y, acc[a][1]))));
        acc[a][2] = fmaf(hv[a].x, wA.z, fmaf(hv[a].y, wB.z, fmaf(hv[a].z, wC.z, fmaf(hv[a].w, wD.z, acc[a][2]))));
        acc[a][3] = fmaf(hv[a].x, wA.w, fmaf(hv[a].y, wB.w, fmaf(hv[a].z, wC.w, fmaf(hv[a].w, wD.w, acc[a][3]))));
      }
    }
  }

  // relu, *W2, partial-reduce over this thread's 4 j
  {
    const float w20 = __ldg(&W2[j0]),     w21 = __ldg(&W2[j0 + 1]);
    const float w22 = __ldg(&W2[j0 + 2]), w23 = __ldg(&W2[j0 + 3]);
    #pragma unroll
    for (int a = 0; a < 4; a++) {
      float p = fmaxf(acc[a][0], 0.0f) * w20 + fmaxf(acc[a][1], 0.0f) * w21
              + fmaxf(acc[a][2], 0.0f) * w22 + fmaxf(acc[a][3], 0.0f) * w23;
      sPart[r0 + a][jg] = p;
    }
  }
  __syncthreads();

  if (tid < MLP_ROWS) {
    float s = __ldg(&b2[0]);
    #pragma unroll
    for (int g = 0; g < 16; g++) s += sPart[tid][g];
    const float ev = 1.0f / (1.0f + expf(-s));
    sE[tid] = ev;
    out_e[rowbase + tid] = ev;
  }
  __syncthreads();

  // Emit he16 = e_row * h (h rows are L1-hot from the k-loop).
  __half2* he2 = (__half2*)g_he;
  for (int i = tid; i < MLP_ROWS * (DD / 4); i += 256) {
    const int r = i >> 6;           // local row
    const int v = i & 63;           // float4 index within row
    const float4 hv = __ldg(&h4[(size_t)r * (DD / 4) + v]);
    const float e = sE[r];
    const size_t base = ((size_t)(rowbase + r) * DD + v * 4) >> 1;
    he2[base]     = __floats2half2_rn(hv.x * e, hv.y * e);
    he2[base + 1] = __floats2half2_rn(hv.z * e, hv.w * e);
  }
}

// ---------------------------------------------------------------------------
// Kernel 2: h_out[i,:] = sum_{j: A[i,j] > 0} he[j,:]
// One block per row, 256 threads = 8 warps.
// Phase 1: 8 front-batched __ldcs uint4 per thread (MLP=8), integer nonzero
//          test, ballot-compaction into per-warp smem segments (no atomics).
// Phase 2: coalesced fp16 gather of he rows (L2-resident), fp32 accumulate.
// ---------------------------------------------------------------------------
__global__ void __launch_bounds__(256) agg_kernel(const float* __restrict__ A,
                                                  float* __restrict__ out) {
  __shared__ unsigned short s_idx[8][1024];
  __shared__ int s_cnt[8];

  const int row = blockIdx.x;
  const int tid = threadIdx.x;
  const int wid = tid >> 5;
  const int lane = tid & 31;
  const unsigned lt = (1u << lane) - 1u;

  const uint4* Arow = (const uint4*)(A + (size_t)row * NN);

  // Front-batch all 8 streaming loads (keeps DRAM queue full).
  uint4 av[8];
  #pragma unroll
  for (int r = 0; r < 8; r++)
    av[r] = __ldcs(Arow + (wid * 256 + r * 32 + lane));

  // Ballot-compaction. a > 0 <=> bit pattern != 0 (values are 0 or positive).
  int cnt = 0;
  unsigned short* seg = s_idx[wid];
  #pragma unroll
  for (int r = 0; r < 8; r++) {
    const int j0 = (wid * 256 + r * 32 + lane) << 2;
    unsigned m;
    m = __ballot_sync(0xFFFFFFFFu, av[r].x != 0u);
    if (av[r].x) seg[cnt + __popc(m & lt)] = (unsigned short)j0;
    cnt += __popc(m);
    m = __ballot_sync(0xFFFFFFFFu, av[r].y != 0u);
    if (av[r].y) seg[cnt + __popc(m & lt)] = (unsigned short)(j0 + 1);
    cnt += __popc(m);
    m = __ballot_sync(0xFFFFFFFFu, av[r].z != 0u);
    if (av[r].z) seg[cnt + __popc(m & lt)] = (unsigned short)(j0 + 2);
    cnt += __popc(m);
    m = __ballot_sync(0xFFFFFFFFu, av[r].w != 0u);
    if (av[r].w) seg[cnt + __popc(m & lt)] = (unsigned short)(j0 + 3);
    cnt += __popc(m);
  }
  if (lane == 0) s_cnt[wid] = cnt;
  __syncthreads();

  // Phase 2: gather fp16 he rows, accumulate fp32.
  const __half* he = (const __half*)g_he;
  float acc = 0.0f;
  #pragma unroll 1
  for (int w = 0; w < 8; w++) {
    const int c = s_cnt[w];
    const unsigned short* sg = s_idx[w];
    int k = 0;
    for (; k + 4 <= c; k += 4) {
      const int j0 = sg[k], j1 = sg[k + 1], j2 = sg[k + 2], j3 = sg[k + 3];
      const float v0 = __half2float(__ldg(&he[(size_t)j0 * DD + tid]));
      const float v1 = __half2float(__ldg(&he[(size_t)j1 * DD + tid]));
      const float v2 = __half2float(__ldg(&he[(size_t)j2 * DD + tid]));
      const float v3 = __half2float(__ldg(&he[(size_t)j3 * DD + tid]));
      acc += v0 + v1 + v2 + v3;
    }
    for (; k < c; k++)
      acc += __half2float(__ldg(&he[(size_t)sg[k] * DD + tid]));
  }

  out[(size_t)row * DD + tid] = acc;
}

// ---------------------------------------------------------------------------
// Inputs (setup_inputs order):
//   0: graph_info [N*N], 1: h [N*D], 2: W1 [D*H], 3: b1 [H], 4: W2 [H], 5: b2 [1]
// Output: h_out [N*D] followed by e [N].
// ---------------------------------------------------------------------------
extern "C" void kernel_launch(void* const* d_in, const int* in_sizes, int n_in,
                              void* d_out, int out_size) {
  const float* A  = (const float*)d_in[0];
  const float* h  = (const float*)d_in[1];
  const float* W1 = (const float*)d_in[2];
  const float* b1 = (const float*)d_in[3];
  const float* W2 = (const float*)d_in[4];
  const float* b2 = (const float*)d_in[5];

  float* out_h = (float*)d_out;                       // [N*D]
  float* out_e = (float*)d_out + (size_t)NN * DD;     // [N]

  mlp_kernel<<<NN / MLP_ROWS, 256>>>(h, W1, b1, W2, b2, out_e);
  agg_kernel<<<NN, 256>>>(A, out_h);
}

// round 3
// speedup vs baseline: 1.5074x; 1.2902x over previous
#include <cuda_runtime.h>
#include <cuda_fp16.h>
#include <math.h>

#define NN 8192
#define DD 256
#define HH 64

// Pre-scaled features: he[j, d] = e_j * h[j, d], fp16 (4 MB, L2-resident).
__device__ __half g_he[NN * DD];

// ---------------------------------------------------------------------------
// Kernel 1: MLP gate + he emission.
//   e = sigmoid(relu(h @ W1 + b1) @ W2 + b2)
// 16 rows/block, 256 threads = 16 rows x 16 j-groups(x4 hidden).
// W1 read directly via __ldg (64 KB, L1-resident); h float4 broadcast loads.
// ---------------------------------------------------------------------------
#define MLP_ROWS 16
__global__ void __launch_bounds__(256) mlp_kernel(
    const float* __restrict__ h, const float* __restrict__ W1,
    const float* __restrict__ b1, const float* __restrict__ W2,
    const float* __restrict__ b2, float* __restrict__ out_e) {

  __shared__ float sPart[MLP_ROWS][17];
  __shared__ float sE[MLP_ROWS];

  const int tid = threadIdx.x;
  const int rg = tid >> 4;                 // 0..15 -> local row
  const int jg = tid & 15;                 // 0..15
  const int j0 = jg * 4;
  const int rowbase = blockIdx.x * MLP_ROWS;
  const int row = rowbase + rg;

  float acc0 = __ldg(&b1[j0]),     acc1 = __ldg(&b1[j0 + 1]);
  float acc2 = __ldg(&b1[j0 + 2]), acc3 = __ldg(&b1[j0 + 3]);

  const float4* hrow = (const float4*)(h + (size_t)row * DD);
  const float4* W14 = (const float4*)W1;   // row k = 16 float4 over j

  #pragma unroll 4
  for (int k4 = 0; k4 < DD / 4; k4++) {
    const float4 hv = __ldg(&hrow[k4]);    // 16-way broadcast within rg group
    const float4 wA = __ldg(&W14[(k4 * 4 + 0) * 16 + jg]);
    const float4 wB = __ldg(&W14[(k4 * 4 + 1) * 16 + jg]);
    const float4 wC = __ldg(&W14[(k4 * 4 + 2) * 16 + jg]);
    const float4 wD = __ldg(&W14[(k4 * 4 + 3) * 16 + jg]);
    acc0 = fmaf(hv.x, wA.x, fmaf(hv.y, wB.x, fmaf(hv.z, wC.x, fmaf(hv.w, wD.x, acc0))));
    acc1 = fmaf(hv.x, wA.y, fmaf(hv.y, wB.y, fmaf(hv.z, wC.y, fmaf(hv.w, wD.y, acc1))));
    acc2 = fmaf(hv.x, wA.z, fmaf(hv.y, wB.z, fmaf(hv.z, wC.z, fmaf(hv.w, wD.z, acc2))));
    acc3 = fmaf(hv.x, wA.w, fmaf(hv.y, wB.w, fmaf(hv.z, wC.w, fmaf(hv.w, wD.w, acc3))));
  }

  {
    const float w20 = __ldg(&W2[j0]),     w21 = __ldg(&W2[j0 + 1]);
    const float w22 = __ldg(&W2[j0 + 2]), w23 = __ldg(&W2[j0 + 3]);
    sPart[rg][jg] = fmaxf(acc0, 0.0f) * w20 + fmaxf(acc1, 0.0f) * w21
                  + fmaxf(acc2, 0.0f) * w22 + fmaxf(acc3, 0.0f) * w23;
  }
  __syncthreads();

  if (tid < MLP_ROWS) {
    float s = __ldg(&b2[0]);
    #pragma unroll
    for (int g = 0; g < 16; g++) s += sPart[tid][g];
    const float ev = 1.0f / (1.0f + expf(-s));
    sE[tid] = ev;
    out_e[rowbase + tid] = ev;
  }
  __syncthreads();

  // Emit he16 = e_row * h  (h rows L1-hot). 16 rows x 64 float4 / 256 thr = 4 ea.
  __half2* he2 = (__half2*)g_he;
  const float4* h4b = (const float4*)(h + (size_t)rowbase * DD);
  #pragma unroll
  for (int i = tid; i < MLP_ROWS * (DD / 4); i += 256) {
    const int r = i >> 6;
    const float4 hv = __ldg(&h4b[i]);
    const float e = sE[r];
    const size_t base = ((size_t)rowbase * DD + i * 4) >> 1;
    he2[base]     = __floats2half2_rn(hv.x * e, hv.y * e);
    he2[base + 1] = __floats2half2_rn(hv.z * e, hv.w * e);
  }
}

// ---------------------------------------------------------------------------
// Kernel 2: h_out[i,:] = sum_{j: A[i,j] > 0} he[j,:]
// One block (256 thr = 8 warps) per output row.
// Scan: 8 front-batched __ldcs uint4/thread; whole-uint4 zero fast path
//       (~96% of vectors skip); rare smem atomicAdd push of indices.
// Gather: warps split nnz; each warp loads a FULL he row per nnz as 32 x
//         uint4 (8 fp16 cols/thread -> 1 warp-LDG.128 per nnz), fp32 accs,
//         cross-warp smem reduce at the end.
// ---------------------------------------------------------------------------
__global__ void __launch_bounds__(256) agg_kernel(const float* __restrict__ A,
                                                  float* __restrict__ out) {
  __shared__ unsigned short s_idx[2048];
  __shared__ int s_cnt;
  __shared__ float s_red[8][DD];

  const int row = blockIdx.x;
  const int tid = threadIdx.x;
  const int wid = tid >> 5;
  const int lane = tid & 31;

  if (tid == 0) s_cnt = 0;
  __syncthreads();

  const uint4* Arow = (const uint4*)(A + (size_t)row * NN);

  // Front-batch all 8 streaming loads (MLP=8, keeps DRAM queue full).
  uint4 av[8];
  #pragma unroll
  for (int r = 0; r < 8; r++)
    av[r] = __ldcs(Arow + tid + r * 256);

  // a > 0  <=>  bit pattern != 0 (values are 0 or positive floats).
  #pragma unroll
  for (int r = 0; r < 8; r++) {
    const uint4 a = av[r];
    if (a.x | a.y | a.z | a.w) {
      const int j0 = (tid + r * 256) << 2;
      if (a.x) s_idx[atomicAdd(&s_cnt, 1)] = (unsigned short)j0;
      if (a.y) s_idx[atomicAdd(&s_cnt, 1)] = (unsigned short)(j0 + 1);
      if (a.z) s_idx[atomicAdd(&s_cnt, 1)] = (unsigned short)(j0 + 2);
      if (a.w) s_idx[atomicAdd(&s_cnt, 1)] = (unsigned short)(j0 + 3);
    }
  }
  __syncthreads();
  const int cnt = s_cnt;

  // Gather: warp w handles nnz k = w, w+8, w+16, ...
  const uint4* he4 = (const uint4*)g_he;   // row j = 32 uint4 (256 halves)
  float acc[8] = {0.f, 0.f, 0.f, 0.f, 0.f, 0.f, 0.f, 0.f};

  int k = wid;
  for (; k + 8 < cnt; k += 16) {           // 2-way unrolled for MLP
    const int ja = s_idx[k];
    const int jb = s_idx[k + 8];
    const uint4 va = __ldg(&he4[(size_t)ja * 32 + lane]);
    const uint4 vb = __ldg(&he4[(size_t)jb * 32 + lane]);
    const __half2* pa = (const __half2*)&va;
    const __half2* pb = (const __half2*)&vb;
    #pragma unroll
    for (int q = 0; q < 4; q++) {
      const float2 fa = __half22float2(pa[q]);
      const float2 fb = __half22float2(pb[q]);
      acc[2 * q]     += fa.x + fb.x;
      acc[2 * q + 1] += fa.y + fb.y;
    }
  }
  if (k < cnt) {
    const int j = s_idx[k];
    const uint4 v = __ldg(&he4[(size_t)j * 32 + lane]);
    const __half2* p = (const __half2*)&v;
    #pragma unroll
    for (int q = 0; q < 4; q++) {
      const float2 f = __half22float2(p[q]);
      acc[2 * q]     += f.x;
      acc[2 * q + 1] += f.y;
    }
  }

  // Cross-warp reduce: thread covers cols lane*8 .. lane*8+7.
  #pragma unroll
  for (int q = 0; q < 8; q++) s_red[wid][lane * 8 + q] = acc[q];
  __syncthreads();

  float s = 0.0f;
  #pragma unroll
  for (int w = 0; w < 8; w++) s += s_red[w][tid];
  out[(size_t)row * DD + tid] = s;
}

// ---------------------------------------------------------------------------
// Inputs (setup_inputs order):
//   0: graph_info [N*N], 1: h [N*D], 2: W1 [D*H], 3: b1 [H], 4: W2 [H], 5: b2 [1]
// Output: h_out [N*D] followed by e [N].
// ---------------------------------------------------------------------------
extern "C" void kernel_launch(void* const* d_in, const int* in_sizes, int n_in,
                              void* d_out, int out_size) {
  const float* A  = (const float*)d_in[0];
  const float* h  = (const float*)d_in[1];
  const float* W1 = (const float*)d_in[2];
  const float* b1 = (const float*)d_in[3];
  const float* W2 = (const float*)d_in[4];
  const float* b2 = (const float*)d_in[5];

  float* out_h = (float*)d_out;                     // [N*D]
  float* out_e = (float*)d_out + (size_t)NN * DD;   // [N]

  mlp_kernel<<<NN / MLP_ROWS, 256>>>(h, W1, b1, W2, b2, out_e);
  agg_kernel<<<NN, 256>>>(A, out_h);
}